// round 1
// baseline (speedup 1.0000x reference)
#include <cuda_runtime.h>

// ---------------------------------------------------------------------------
// Causal self-attention, fp32 SIMT baseline.
//   q = x@Wq + bq ; k = x@Wk + bk ; v = x@Wv + bv
//   scores = q k^T (causal mask) ; P = softmax(scores) ; out = P v
// ---------------------------------------------------------------------------

namespace cfg {
constexpr int B = 4;
constexpr int S = 2048;
constexpr int D = 1024;
constexpr int MR = B * S;           // 8192 folded rows for the projections
constexpr int BM = 128, BN = 128, BK = 16;
constexpr int TM = 8, TN = 8;
}

// Scratch (allocation-free rule: __device__ globals)
__device__ float g_q[cfg::MR * cfg::D];
__device__ float g_k[cfg::MR * cfg::D];
__device__ float g_v[cfg::MR * cfg::D];
__device__ float g_p[(long long)cfg::B * cfg::S * cfg::S];   // scores -> probs in place

// ---------------------------------------------------------------------------
// Templated tiled SGEMM.
//   C[m,n] = sum_k A[m,k] * B(k,n)   (+ bias[n])
//   TRANSB: B stored row-major [N,K] (used for Q K^T)
//   CAUSAL_SKIP: skip tiles entirely above the diagonal (scores)
//   KBOUND: K-loop bounded at m0+BM (P is zero for k > m; used for P V)
// All dims are multiples of tile sizes -> no bounds checks.
// ---------------------------------------------------------------------------
template <bool TRANSB, bool HAS_BIAS, bool CAUSAL_SKIP, bool KBOUND>
__global__ __launch_bounds__(256) void gemm_kernel(
    const float* __restrict__ A, const float* __restrict__ Bm,
    const float* __restrict__ bias, float* __restrict__ C,
    int Ndim, int Kdim,
    long long sA, long long sB, long long sC)
{
    using namespace cfg;
    const int m0 = blockIdx.y * BM;
    const int n0 = blockIdx.x * BN;
    if (CAUSAL_SKIP && n0 > m0 + (BM - 1)) return;   // fully-masked tile

    const float* Ab = A  + (long long)blockIdx.z * sA;
    const float* Bb = Bm + (long long)blockIdx.z * sB;
    float*       Cb = C  + (long long)blockIdx.z * sC;

    __shared__ float As[BK][BM];
    __shared__ float Bs[BK][BN];

    const int tid = threadIdx.x;
    const int tx  = tid & 15;        // 16 thread cols
    const int ty  = tid >> 4;        // 16 thread rows

    // A-tile (and transposed-B-tile) load mapping: 2 x float4 per thread
    const int arow = tid >> 2;       // 0..63
    const int acol = (tid & 3) << 2; // 0,4,8,12
    // NN B-tile load mapping
    const int brow = tid >> 5;       // 0..7
    const int bcol = (tid & 31) << 2;

    float acc[TM][TN];
#pragma unroll
    for (int i = 0; i < TM; i++)
#pragma unroll
        for (int j = 0; j < TN; j++) acc[i][j] = 0.f;

    const int kEnd = KBOUND ? (m0 + BM) : Kdim;

    for (int k0 = 0; k0 < kEnd; k0 += BK) {
        // ---- stage A tile, transposed: As[k][m]
        float4 a0 = *(const float4*)(Ab + (long long)(m0 + arow)      * Kdim + k0 + acol);
        float4 a1 = *(const float4*)(Ab + (long long)(m0 + arow + 64) * Kdim + k0 + acol);
        As[acol + 0][arow]      = a0.x;
        As[acol + 1][arow]      = a0.y;
        As[acol + 2][arow]      = a0.z;
        As[acol + 3][arow]      = a0.w;
        As[acol + 0][arow + 64] = a1.x;
        As[acol + 1][arow + 64] = a1.y;
        As[acol + 2][arow + 64] = a1.z;
        As[acol + 3][arow + 64] = a1.w;

        if (TRANSB) {
            // B row-major [N, K] -> Bs[k][n]
            float4 b0 = *(const float4*)(Bb + (long long)(n0 + arow)      * Kdim + k0 + acol);
            float4 b1 = *(const float4*)(Bb + (long long)(n0 + arow + 64) * Kdim + k0 + acol);
            Bs[acol + 0][arow]      = b0.x;
            Bs[acol + 1][arow]      = b0.y;
            Bs[acol + 2][arow]      = b0.z;
            Bs[acol + 3][arow]      = b0.w;
            Bs[acol + 0][arow + 64] = b1.x;
            Bs[acol + 1][arow + 64] = b1.y;
            Bs[acol + 2][arow + 64] = b1.z;
            Bs[acol + 3][arow + 64] = b1.w;
        } else {
            // B row-major [K, N] -> Bs[k][n] directly
            float4 b0 = *(const float4*)(Bb + (long long)(k0 + brow)     * Ndim + n0 + bcol);
            float4 b1 = *(const float4*)(Bb + (long long)(k0 + brow + 8) * Ndim + n0 + bcol);
            *(float4*)&Bs[brow][bcol]     = b0;
            *(float4*)&Bs[brow + 8][bcol] = b1;
        }
        __syncthreads();

#pragma unroll
        for (int kk = 0; kk < BK; kk++) {
            float a[TM], b[TN];
            *(float4*)&a[0] = *(const float4*)&As[kk][ty * TM];
            *(float4*)&a[4] = *(const float4*)&As[kk][ty * TM + 4];
            *(float4*)&b[0] = *(const float4*)&Bs[kk][tx * TN];
            *(float4*)&b[4] = *(const float4*)&Bs[kk][tx * TN + 4];
#pragma unroll
            for (int i = 0; i < TM; i++)
#pragma unroll
                for (int j = 0; j < TN; j++)
                    acc[i][j] = fmaf(a[i], b[j], acc[i][j]);
        }
        __syncthreads();
    }

    // ---- epilogue
#pragma unroll
    for (int i = 0; i < TM; i++) {
        const long long m = m0 + ty * TM + i;
#pragma unroll
        for (int j = 0; j < TN; j += 4) {
            const int n = n0 + tx * TN + j;
            float4 r;
            r.x = acc[i][j + 0];
            r.y = acc[i][j + 1];
            r.z = acc[i][j + 2];
            r.w = acc[i][j + 3];
            if (HAS_BIAS) {
                r.x += bias[n + 0];
                r.y += bias[n + 1];
                r.z += bias[n + 2];
                r.w += bias[n + 3];
            }
            *(float4*)(Cb + m * Ndim + n) = r;
        }
    }
}

// ---------------------------------------------------------------------------
// Causal row softmax, in place. One block per (b, q) row.
// Reads scores[0..q], writes normalized probs; zeroes [q+1, S) so the PV GEMM
// can safely run its tile-bounded K loop.
// ---------------------------------------------------------------------------
__global__ __launch_bounds__(256) void softmax_causal(float* __restrict__ P)
{
    using namespace cfg;
    const int row = blockIdx.x;             // 0 .. B*S-1
    const int b   = row / S;
    const int q   = row - b * S;
    float* p = P + (long long)b * S * S + (long long)q * S;
    const int len = q + 1;
    const int tid = threadIdx.x;

    __shared__ float red[256];

    // max
    float m = -3.4e38f;
    for (int i = tid; i < len; i += 256) m = fmaxf(m, p[i]);
    red[tid] = m;
    __syncthreads();
#pragma unroll
    for (int s2 = 128; s2 > 0; s2 >>= 1) {
        if (tid < s2) red[tid] = fmaxf(red[tid], red[tid + s2]);
        __syncthreads();
    }
    m = red[0];
    __syncthreads();

    // exp + sum
    float sum = 0.f;
    for (int i = tid; i < len; i += 256) {
        float e = __expf(p[i] - m);
        p[i] = e;
        sum += e;
    }
    red[tid] = sum;
    __syncthreads();
#pragma unroll
    for (int s2 = 128; s2 > 0; s2 >>= 1) {
        if (tid < s2) red[tid] += red[tid + s2];
        __syncthreads();
    }
    const float inv = 1.f / red[0];
    __syncthreads();

    // normalize + zero the masked tail
    for (int i = tid; i < len; i += 256) p[i] *= inv;
    for (int i = len + tid; i < S; i += 256) p[i] = 0.f;
}

// ---------------------------------------------------------------------------
// Launch
// ---------------------------------------------------------------------------
extern "C" void kernel_launch(void* const* d_in, const int* in_sizes, int n_in,
                              void* d_out, int out_size)
{
    using namespace cfg;
    const float* x  = (const float*)d_in[0];
    const float* Wq = (const float*)d_in[1];
    const float* bq = (const float*)d_in[2];
    const float* Wk = (const float*)d_in[3];
    const float* bk = (const float*)d_in[4];
    const float* Wv = (const float*)d_in[5];
    const float* bv = (const float*)d_in[6];
    float* out = (float*)d_out;

    float *q, *k, *v, *p;
    cudaGetSymbolAddress((void**)&q, g_q);
    cudaGetSymbolAddress((void**)&k, g_k);
    cudaGetSymbolAddress((void**)&v, g_v);
    cudaGetSymbolAddress((void**)&p, g_p);

    dim3 blk(256);

    // QKV projections: [8192,1024] @ [1024,1024] + bias
    dim3 gproj(D / BN, MR / BM, 1);
    gemm_kernel<false, true, false, false><<<gproj, blk>>>(x, Wq, bq, q, D, D, 0, 0, 0);
    gemm_kernel<false, true, false, false><<<gproj, blk>>>(x, Wk, bk, k, D, D, 0, 0, 0);
    gemm_kernel<false, true, false, false><<<gproj, blk>>>(x, Wv, bv, v, D, D, 0, 0, 0);

    // scores = Q K^T per batch, causal tile-skip
    dim3 gsc(S / BN, S / BM, B);
    gemm_kernel<true, false, true, false><<<gsc, blk>>>(
        q, k, nullptr, p, S, D,
        (long long)S * D, (long long)S * D, (long long)S * S);

    // causal softmax in place
    softmax_causal<<<B * S, 256>>>(p);

    // out = P V per batch, K loop bounded by causal structure
    dim3 gpv(D / BN, S / BM, B);
    gemm_kernel<false, false, false, true><<<gpv, blk>>>(
        p, v, nullptr, out, D, S,
        (long long)S * S, (long long)S * D, (long long)S * D);
}

// round 3
// speedup vs baseline: 2.5529x; 2.5529x over previous
#include <cuda_runtime.h>
#include <cuda_bf16.h>
#include <cstdint>

// ===========================================================================
// Causal self-attention via mma.sync bf16 (sm_103 non-'a' compatible).
// All GEMMs: bf16 3-term hi/lo split (fp32-accurate), fp32 accumulate.
//   q=x@Wq+bq; k=x@Wk+bk; v=x@Wv+bv; s=qk^T (causal); P=softmax(s); out=P v
// ===========================================================================

namespace cfg {
constexpr int B = 4;
constexpr int S = 2048;
constexpr int D = 1024;
constexpr int MR = B * S;          // 8192
}

// ---------------- scratch (__device__ globals; no allocations) -------------
__device__ float g_q[cfg::MR * cfg::D];
__device__ float g_k[cfg::MR * cfg::D];
__device__ float g_v[cfg::MR * cfg::D];
__device__ float g_p[(long long)cfg::B * cfg::S * cfg::S];

// bf16 hi/lo planes, stored as [rows][2K] = [hi(0..K-1) | lo(0..K-1)]
__device__ unsigned short g_x2 [(long long)cfg::MR * 2 * cfg::D];
__device__ unsigned short g_wq2[(long long)cfg::D  * 2 * cfg::D];   // [n][2K], W^T
__device__ unsigned short g_wk2[(long long)cfg::D  * 2 * cfg::D];
__device__ unsigned short g_wv2[(long long)cfg::D  * 2 * cfg::D];
__device__ unsigned short g_q2 [(long long)cfg::MR * 2 * cfg::D];
__device__ unsigned short g_k2 [(long long)cfg::MR * 2 * cfg::D];
__device__ unsigned short g_v2t[(long long)cfg::B * cfg::D * 2 * cfg::S]; // [b][d][2S], V^T
__device__ unsigned short g_p2 [(long long)cfg::B * cfg::S * 2 * cfg::S];

// ---------------- PTX helpers ----------------------------------------------
__device__ __forceinline__ uint32_t smem_u32(const void* p) {
    uint32_t a;
    asm("{ .reg .u64 t; cvta.to.shared.u64 t, %1; cvt.u32.u64 %0, t; }"
        : "=r"(a) : "l"(p));
    return a;
}

#define CP_ASYNC_16(dst, src)                                                 \
    asm volatile("cp.async.cg.shared.global [%0], [%1], 16;"                  \
                 :: "r"(dst), "l"(src))
#define CP_COMMIT() asm volatile("cp.async.commit_group;" ::: "memory")
#define CP_WAIT_1() asm volatile("cp.async.wait_group 1;" ::: "memory")
#define CP_WAIT_0() asm volatile("cp.async.wait_group 0;" ::: "memory")

#define LDSM_X4(r0, r1, r2, r3, addr)                                         \
    asm volatile("ldmatrix.sync.aligned.m8n8.x4.shared.b16 {%0,%1,%2,%3}, [%4];" \
                 : "=r"(r0), "=r"(r1), "=r"(r2), "=r"(r3) : "r"(addr))

#define MMA_BF16(d, a, b)                                                     \
    asm volatile("mma.sync.aligned.m16n8k16.row.col.f32.bf16.bf16.f32 "       \
                 "{%0,%1,%2,%3},{%4,%5,%6,%7},{%8,%9},{%0,%1,%2,%3};"         \
                 : "+f"((d)[0]), "+f"((d)[1]), "+f"((d)[2]), "+f"((d)[3])     \
                 : "r"((a)[0]), "r"((a)[1]), "r"((a)[2]), "r"((a)[3]),        \
                   "r"((b)[0]), "r"((b)[1]))

// ---------------- hi/lo split helper ---------------------------------------
__device__ __forceinline__ void split1(float v, unsigned short& h, unsigned short& l) {
    __nv_bfloat16 hb = __float2bfloat16(v);
    float rem = v - __bfloat162float(hb);
    __nv_bfloat16 lb = __float2bfloat16(rem);
    h = __bfloat16_as_ushort(hb);
    l = __bfloat16_as_ushort(lb);
}

// fp32 [rows][K] -> bf16 [rows][2K] (hi plane | lo plane)
__global__ __launch_bounds__(256) void conv_split(
    const float* __restrict__ in, unsigned short* __restrict__ out,
    unsigned int total4, unsigned int Kq /* = K/4 */, int K)
{
    for (unsigned int i = blockIdx.x * blockDim.x + threadIdx.x; i < total4;
         i += gridDim.x * blockDim.x) {
        unsigned int r = i / Kq;
        unsigned int c4 = i - r * Kq;
        float4 v = *(const float4*)(in + (long long)r * K + c4 * 4);
        unsigned short h0, h1, h2, h3, l0, l1, l2, l3;
        split1(v.x, h0, l0); split1(v.y, h1, l1);
        split1(v.z, h2, l2); split1(v.w, h3, l3);
        uint2 hv, lv;
        hv.x = (uint32_t)h0 | ((uint32_t)h1 << 16);
        hv.y = (uint32_t)h2 | ((uint32_t)h3 << 16);
        lv.x = (uint32_t)l0 | ((uint32_t)l1 << 16);
        lv.y = (uint32_t)l2 | ((uint32_t)l3 << 16);
        unsigned short* orow = out + (long long)r * 2 * K;
        *(uint2*)(orow + c4 * 4)     = hv;
        *(uint2*)(orow + K + c4 * 4) = lv;
    }
}

// fp32 [Krows][Ncols] -> bf16 [Ncols][2*Krows] transposed hi/lo (for W^T, V^T)
__global__ __launch_bounds__(256) void conv_split_T(
    const float* __restrict__ in, unsigned short* __restrict__ out,
    int Krows, int Ncols, long long sIn, long long sOut)
{
    __shared__ float t[32][33];
    const float* ib = in + (long long)blockIdx.z * sIn;
    unsigned short* ob = out + (long long)blockIdx.z * sOut;
    const int k0 = blockIdx.y * 32, n0 = blockIdx.x * 32;
    const int tx = threadIdx.x, ty = threadIdx.y;     // (32, 8)
#pragma unroll
    for (int i = 0; i < 4; i++)
        t[ty + i * 8][tx] = ib[(long long)(k0 + ty + i * 8) * Ncols + n0 + tx];
    __syncthreads();
    const int ld2 = 2 * Krows;
#pragma unroll
    for (int i = 0; i < 4; i++) {
        int n = n0 + ty + i * 8;
        int k = k0 + tx;
        unsigned short h, l;
        split1(t[tx][ty + i * 8], h, l);
        ob[(long long)n * ld2 + k]         = h;
        ob[(long long)n * ld2 + Krows + k] = l;
    }
}

// ===========================================================================
// mma.sync GEMM: C[m,n] = sum over 3 bf16 term-pairs of A2,B2 (+bias)
//   A2: [M][2K] hi|lo, segments {hi,hi,lo};  B2: [N][2K] hi|lo, segs {hi,lo,hi}
// 128x128 tile, BK=64 bf16, 3-stage cp.async pipeline, warp tile 64x32.
// ===========================================================================
template <bool HAS_BIAS, bool CAUSAL_SKIP, bool KBOUND>
__global__ __launch_bounds__(256, 2) void mma_gemm(
    const unsigned short* __restrict__ A2, const unsigned short* __restrict__ B2,
    const float* __restrict__ bias, float* __restrict__ C,
    int Ndim, int Kdim, long long sA, long long sB, long long sC)
{
    const int m0 = blockIdx.y * 128;
    const int n0 = blockIdx.x * 128;
    if (CAUSAL_SKIP && n0 > m0 + 127) return;

    extern __shared__ char dynsmem[];
    const uint32_t sb = smem_u32(dynsmem);
    // 3 stages, each: A tile 16KB @ +0, B tile 16KB @ +16384 (stage stride 32768)

    const int tid  = threadIdx.x;
    const int lane = tid & 31;
    const int warp = tid >> 5;
    const int wm   = warp >> 2;       // 0..1
    const int wn   = warp & 3;        // 0..3

    const long long ldAe = 2LL * Kdim;            // elements per row
    const long long ldBytes = ldAe * 2;
    const char* baseA = (const char*)(A2 + (long long)blockIdx.z * sA + (long long)m0 * ldAe);
    const char* baseB = (const char*)(B2 + (long long)blockIdx.z * sB + (long long)n0 * ldAe);
    float* Cb = C + (long long)blockIdx.z * sC;

    const int segK = KBOUND ? (m0 + 128) : Kdim;
    const int nps = segK >> 6;                    // 64-elem chunks per segment
    const int nChunks = 3 * nps;

    // ---- staging mapping: thread -> (row, 16B chunk), 4 rows apart by 32
    const int srow = tid >> 3;                    // 0..31
    const int su   = tid & 7;                     // 0..7
    const uint32_t sdst = (uint32_t)(srow * 128 + ((su ^ (srow & 7)) << 4));
    const long long sgoff = (long long)srow * ldBytes + su * 16;

    auto stage = [&](int c, int buf) {
        const int seg = c / nps, kc = c - seg * nps;
        const long long offA = ((long long)kc * 64 + (seg == 2 ? (long long)Kdim : 0)) * 2;
        const long long offB = ((long long)kc * 64 + (seg == 1 ? (long long)Kdim : 0)) * 2;
        const char* ga = baseA + offA + sgoff;
        const char* gb = baseB + offB + sgoff;
        const uint32_t da = sb + buf * 32768u + sdst;
        const uint32_t db = da + 16384u;
#pragma unroll
        for (int i = 0; i < 4; i++) {
            CP_ASYNC_16(da + i * 4096u, ga + (long long)i * 32 * ldBytes);
            CP_ASYNC_16(db + i * 4096u, gb + (long long)i * 32 * ldBytes);
        }
        CP_COMMIT();
    };

    float acc[4][4][4];
#pragma unroll
    for (int i = 0; i < 4; i++)
#pragma unroll
        for (int j = 0; j < 4; j++)
#pragma unroll
            for (int t = 0; t < 4; t++) acc[i][j][t] = 0.f;

    // per-lane ldmatrix address components (XOR swizzle: chunk ^= row&7 = lane&7)
    const uint32_t aRowBase = (uint32_t)(wm * 64 + (lane & 15));
    const uint32_t aChunkX  = (uint32_t)(lane >> 4);            // +s*2, ^lane&7
    const uint32_t bRowBase = (uint32_t)(wn * 32 + (lane & 7) + ((lane & 16) >> 1));
    const uint32_t bChunkX  = (uint32_t)((lane >> 3) & 1);
    const uint32_t lxor     = (uint32_t)(lane & 7);

    stage(0, 0);
    stage(1, 1);

    for (int c = 0; c < nChunks; c++) {
        if (c + 1 < nChunks) { CP_WAIT_1(); } else { CP_WAIT_0(); }
        __syncthreads();

        const uint32_t sA = sb + (uint32_t)(c % 3) * 32768u;
        const uint32_t sB = sA + 16384u;

#pragma unroll
        for (int s = 0; s < 4; s++) {
            uint32_t a[4][4];
            uint32_t b[4][2];
#pragma unroll
            for (int mb = 0; mb < 4; mb++) {
                const uint32_t addr = sA + (aRowBase + mb * 16) * 128u
                                    + (((s * 2 + aChunkX) ^ lxor) << 4);
                LDSM_X4(a[mb][0], a[mb][1], a[mb][2], a[mb][3], addr);
            }
#pragma unroll
            for (int nb2 = 0; nb2 < 2; nb2++) {
                const uint32_t addr = sB + (bRowBase + nb2 * 16) * 128u
                                    + (((s * 2 + bChunkX) ^ lxor) << 4);
                LDSM_X4(b[nb2 * 2][0], b[nb2 * 2][1],
                        b[nb2 * 2 + 1][0], b[nb2 * 2 + 1][1], addr);
            }
#pragma unroll
            for (int mb = 0; mb < 4; mb++)
#pragma unroll
                for (int nb = 0; nb < 4; nb++)
                    MMA_BF16(acc[mb][nb], a[mb], b[nb]);
        }

        if (c + 2 < nChunks) stage(c + 2, (c + 2) % 3);
    }

    // ---- epilogue: direct fp32 stores (+bias) ------------------------------
    const int rBase = m0 + wm * 64 + (lane >> 2);
    const int cBase = n0 + wn * 32 + (lane & 3) * 2;
#pragma unroll
    for (int nb = 0; nb < 4; nb++) {
        const int cc = cBase + nb * 8;
        float bx = 0.f, by = 0.f;
        if (HAS_BIAS) { bx = bias[cc]; by = bias[cc + 1]; }
#pragma unroll
        for (int mb = 0; mb < 4; mb++) {
            const int r = rBase + mb * 16;
            float2 v0, v1;
            v0.x = acc[mb][nb][0] + bx; v0.y = acc[mb][nb][1] + by;
            v1.x = acc[mb][nb][2] + bx; v1.y = acc[mb][nb][3] + by;
            *(float2*)(Cb + (long long)r * Ndim + cc)       = v0;
            *(float2*)(Cb + (long long)(r + 8) * Ndim + cc) = v1;
        }
    }
}

// ---------------- causal softmax (in place) ---------------------------------
__global__ __launch_bounds__(256) void softmax_causal(float* __restrict__ P)
{
    using namespace cfg;
    const int row = blockIdx.x;
    const int b = row / S;
    const int q = row - b * S;
    float* p = P + (long long)b * S * S + (long long)q * S;
    const int len = q + 1;
    const int tid = threadIdx.x;
    __shared__ float red[256];

    float m = -3.4e38f;
    for (int i = tid; i < len; i += 256) m = fmaxf(m, p[i]);
    red[tid] = m;
    __syncthreads();
#pragma unroll
    for (int s2 = 128; s2 > 0; s2 >>= 1) {
        if (tid < s2) red[tid] = fmaxf(red[tid], red[tid + s2]);
        __syncthreads();
    }
    m = red[0];
    __syncthreads();

    float sum = 0.f;
    for (int i = tid; i < len; i += 256) {
        float e = __expf(p[i] - m);
        p[i] = e;
        sum += e;
    }
    red[tid] = sum;
    __syncthreads();
#pragma unroll
    for (int s2 = 128; s2 > 0; s2 >>= 1) {
        if (tid < s2) red[tid] += red[tid + s2];
        __syncthreads();
    }
    const float inv = 1.f / red[0];
    __syncthreads();

    for (int i = tid; i < len; i += 256) p[i] *= inv;
    for (int i = len + tid; i < S; i += 256) p[i] = 0.f;
}

// ===========================================================================
// launch
// ===========================================================================
extern "C" void kernel_launch(void* const* d_in, const int* in_sizes, int n_in,
                              void* d_out, int out_size)
{
    using namespace cfg;
    const float* x  = (const float*)d_in[0];
    const float* Wq = (const float*)d_in[1];
    const float* bq = (const float*)d_in[2];
    const float* Wk = (const float*)d_in[3];
    const float* bk = (const float*)d_in[4];
    const float* Wv = (const float*)d_in[5];
    const float* bv = (const float*)d_in[6];
    float* out = (float*)d_out;

    float *q, *k, *v, *p;
    unsigned short *x2, *wq2, *wk2, *wv2, *q2, *k2, *v2t, *p2;
    cudaGetSymbolAddress((void**)&q, g_q);
    cudaGetSymbolAddress((void**)&k, g_k);
    cudaGetSymbolAddress((void**)&v, g_v);
    cudaGetSymbolAddress((void**)&p, g_p);
    cudaGetSymbolAddress((void**)&x2,  g_x2);
    cudaGetSymbolAddress((void**)&wq2, g_wq2);
    cudaGetSymbolAddress((void**)&wk2, g_wk2);
    cudaGetSymbolAddress((void**)&wv2, g_wv2);
    cudaGetSymbolAddress((void**)&q2,  g_q2);
    cudaGetSymbolAddress((void**)&k2,  g_k2);
    cudaGetSymbolAddress((void**)&v2t, g_v2t);
    cudaGetSymbolAddress((void**)&p2,  g_p2);

    const int SMEM_DYN = 98304;   // 3 stages x (16KB A + 16KB B)
    cudaFuncSetAttribute(mma_gemm<true,  false, false>,
                         cudaFuncAttributeMaxDynamicSharedMemorySize, SMEM_DYN);
    cudaFuncSetAttribute(mma_gemm<false, true,  false>,
                         cudaFuncAttributeMaxDynamicSharedMemorySize, SMEM_DYN);
    cudaFuncSetAttribute(mma_gemm<false, false, true>,
                         cudaFuncAttributeMaxDynamicSharedMemorySize, SMEM_DYN);

    // 1) split x into hi/lo bf16 planes
    conv_split<<<8192, 256>>>(x, x2, (unsigned)(MR * D / 4), (unsigned)(D / 4), D);
    // 2) W^T hi/lo (transpose + split)
    {
        dim3 g(D / 32, D / 32, 1), b2(32, 8);
        conv_split_T<<<g, b2>>>(Wq, wq2, D, D, 0, 0);
        conv_split_T<<<g, b2>>>(Wk, wk2, D, D, 0, 0);
        conv_split_T<<<g, b2>>>(Wv, wv2, D, D, 0, 0);
    }
    // 3) projections: [8192,1024] = x2 @ W^T  (+bias)
    {
        dim3 g(D / 128, MR / 128, 1), b2(256);
        mma_gemm<true, false, false><<<g, b2, SMEM_DYN>>>(x2, wq2, bq, q, D, D, 0, 0, 0);
        mma_gemm<true, false, false><<<g, b2, SMEM_DYN>>>(x2, wk2, bk, k, D, D, 0, 0, 0);
        mma_gemm<true, false, false><<<g, b2, SMEM_DYN>>>(x2, wv2, bv, v, D, D, 0, 0, 0);
    }
    // 4) split q, k
    conv_split<<<8192, 256>>>(q, q2, (unsigned)(MR * D / 4), (unsigned)(D / 4), D);
    conv_split<<<8192, 256>>>(k, k2, (unsigned)(MR * D / 4), (unsigned)(D / 4), D);
    // 5) scores = q k^T per batch (causal tile skip)
    {
        dim3 g(S / 128, S / 128, B), b2(256);
        mma_gemm<false, true, false><<<g, b2, SMEM_DYN>>>(
            q2, k2, nullptr, p, S, D,
            (long long)S * 2 * D, (long long)S * 2 * D, (long long)S * S);
    }
    // 6) softmax
    softmax_causal<<<B * S, 256>>>(p);
    // 7) split P
    conv_split<<<16384, 256>>>(p, p2, (unsigned)((long long)B * S * S / 4),
                               (unsigned)(S / 4), S);
    // 8) V^T hi/lo per batch
    {
        dim3 g(D / 32, S / 32, B), b2(32, 8);
        conv_split_T<<<g, b2>>>(v, v2t, S, D, (long long)S * D, (long long)D * 2 * S);
    }
    // 9) out = P V per batch (K bounded by causal structure)
    {
        dim3 g(D / 128, S / 128, B), b2(256);
        mma_gemm<false, false, true><<<g, b2, SMEM_DYN>>>(
            p2, v2t, nullptr, out, D, S,
            (long long)S * 2 * S, (long long)D * 2 * S, (long long)S * D);
    }
}

// round 4
// speedup vs baseline: 2.6783x; 1.0491x over previous
#include <cuda_runtime.h>
#include <cuda_bf16.h>
#include <cstdint>

// ===========================================================================
// Causal self-attention via mma.sync bf16 (sm_103 non-'a' compatible).
// All GEMMs: bf16 3-term hi/lo split (fp32-accurate), fp32 accumulate.
// Fusions: QK projections emit bf16 split planes from the epilogue;
//          softmax is register-resident and emits split planes directly.
// ===========================================================================

namespace cfg {
constexpr int B = 4;
constexpr int S = 2048;
constexpr int D = 1024;
constexpr int MR = B * S;          // 8192
}

// ---------------- scratch (__device__ globals; no allocations) -------------
__device__ float g_v[cfg::MR * cfg::D];
__device__ float g_p[(long long)cfg::B * cfg::S * cfg::S];

// bf16 hi/lo planes, stored as [rows][2K] = [hi(0..K-1) | lo(0..K-1)]
__device__ unsigned short g_x2 [(long long)cfg::MR * 2 * cfg::D];
__device__ unsigned short g_wq2[(long long)cfg::D  * 2 * cfg::D];   // [n][2K], W^T
__device__ unsigned short g_wk2[(long long)cfg::D  * 2 * cfg::D];
__device__ unsigned short g_wv2[(long long)cfg::D  * 2 * cfg::D];
__device__ unsigned short g_q2 [(long long)cfg::MR * 2 * cfg::D];
__device__ unsigned short g_k2 [(long long)cfg::MR * 2 * cfg::D];
__device__ unsigned short g_v2t[(long long)cfg::B * cfg::D * 2 * cfg::S]; // [b][d][2S], V^T
__device__ unsigned short g_p2 [(long long)cfg::B * cfg::S * 2 * cfg::S];

// ---------------- PTX helpers ----------------------------------------------
__device__ __forceinline__ uint32_t smem_u32(const void* p) {
    uint32_t a;
    asm("{ .reg .u64 t; cvta.to.shared.u64 t, %1; cvt.u32.u64 %0, t; }"
        : "=r"(a) : "l"(p));
    return a;
}

#define CP_ASYNC_16(dst, src)                                                 \
    asm volatile("cp.async.cg.shared.global [%0], [%1], 16;"                  \
                 :: "r"(dst), "l"(src))
#define CP_COMMIT() asm volatile("cp.async.commit_group;" ::: "memory")
#define CP_WAIT_1() asm volatile("cp.async.wait_group 1;" ::: "memory")
#define CP_WAIT_0() asm volatile("cp.async.wait_group 0;" ::: "memory")

#define LDSM_X4(r0, r1, r2, r3, addr)                                         \
    asm volatile("ldmatrix.sync.aligned.m8n8.x4.shared.b16 {%0,%1,%2,%3}, [%4];" \
                 : "=r"(r0), "=r"(r1), "=r"(r2), "=r"(r3) : "r"(addr))

#define MMA_BF16(d, a, b)                                                     \
    asm volatile("mma.sync.aligned.m16n8k16.row.col.f32.bf16.bf16.f32 "       \
                 "{%0,%1,%2,%3},{%4,%5,%6,%7},{%8,%9},{%0,%1,%2,%3};"         \
                 : "+f"((d)[0]), "+f"((d)[1]), "+f"((d)[2]), "+f"((d)[3])     \
                 : "r"((a)[0]), "r"((a)[1]), "r"((a)[2]), "r"((a)[3]),        \
                   "r"((b)[0]), "r"((b)[1]))

// ---------------- hi/lo split helper ---------------------------------------
__device__ __forceinline__ void split1(float v, unsigned short& h, unsigned short& l) {
    __nv_bfloat16 hb = __float2bfloat16(v);
    float rem = v - __bfloat162float(hb);
    __nv_bfloat16 lb = __float2bfloat16(rem);
    h = __bfloat16_as_ushort(hb);
    l = __bfloat16_as_ushort(lb);
}

// fp32 [rows][K] -> bf16 [rows][2K] (hi plane | lo plane)
__global__ __launch_bounds__(256) void conv_split(
    const float* __restrict__ in, unsigned short* __restrict__ out,
    unsigned int total4, unsigned int Kq /* = K/4 */, int K)
{
    for (unsigned int i = blockIdx.x * blockDim.x + threadIdx.x; i < total4;
         i += gridDim.x * blockDim.x) {
        unsigned int r = i / Kq;
        unsigned int c4 = i - r * Kq;
        float4 v = *(const float4*)(in + (long long)r * K + c4 * 4);
        unsigned short h0, h1, h2, h3, l0, l1, l2, l3;
        split1(v.x, h0, l0); split1(v.y, h1, l1);
        split1(v.z, h2, l2); split1(v.w, h3, l3);
        uint2 hv, lv;
        hv.x = (uint32_t)h0 | ((uint32_t)h1 << 16);
        hv.y = (uint32_t)h2 | ((uint32_t)h3 << 16);
        lv.x = (uint32_t)l0 | ((uint32_t)l1 << 16);
        lv.y = (uint32_t)l2 | ((uint32_t)l3 << 16);
        unsigned short* orow = out + (long long)r * 2 * K;
        *(uint2*)(orow + c4 * 4)     = hv;
        *(uint2*)(orow + K + c4 * 4) = lv;
    }
}

// fp32 [Krows][Ncols] -> bf16 [Ncols][2*Krows] transposed hi/lo (for W^T, V^T)
__global__ __launch_bounds__(256) void conv_split_T(
    const float* __restrict__ in, unsigned short* __restrict__ out,
    int Krows, int Ncols, long long sIn, long long sOut)
{
    __shared__ float t[32][33];
    const float* ib = in + (long long)blockIdx.z * sIn;
    unsigned short* ob = out + (long long)blockIdx.z * sOut;
    const int k0 = blockIdx.y * 32, n0 = blockIdx.x * 32;
    const int tx = threadIdx.x, ty = threadIdx.y;     // (32, 8)
#pragma unroll
    for (int i = 0; i < 4; i++)
        t[ty + i * 8][tx] = ib[(long long)(k0 + ty + i * 8) * Ncols + n0 + tx];
    __syncthreads();
    const int ld2 = 2 * Krows;
#pragma unroll
    for (int i = 0; i < 4; i++) {
        int n = n0 + ty + i * 8;
        int k = k0 + tx;
        unsigned short h, l;
        split1(t[tx][ty + i * 8], h, l);
        ob[(long long)n * ld2 + k]         = h;
        ob[(long long)n * ld2 + Krows + k] = l;
    }
}

// ===========================================================================
// mma.sync GEMM: C[m,n] = sum over 3 bf16 term-pairs of A2,B2 (+bias)
//   A2: [M][2K] hi|lo, segments {hi,hi,lo};  B2: [N][2K] hi|lo, segs {hi,lo,hi}
// 128x128 tile, BK=64 bf16, 3-stage cp.async pipeline, warp tile 64x32.
// EPI_SPLIT: C is ushort* [M][2N] hi|lo (fused output split for Q/K).
// ===========================================================================
template <bool HAS_BIAS, bool CAUSAL_SKIP, bool KBOUND, bool EPI_SPLIT>
__global__ __launch_bounds__(256, 2) void mma_gemm(
    const unsigned short* __restrict__ A2, const unsigned short* __restrict__ B2,
    const float* __restrict__ bias, void* __restrict__ Cv,
    int Ndim, int Kdim, long long sA, long long sB, long long sC)
{
    const int m0 = blockIdx.y * 128;
    const int n0 = blockIdx.x * 128;
    if (CAUSAL_SKIP && n0 > m0 + 127) return;

    extern __shared__ char dynsmem[];
    const uint32_t sb = smem_u32(dynsmem);
    // 3 stages, each: A tile 16KB @ +0, B tile 16KB @ +16384 (stage stride 32768)

    const int tid  = threadIdx.x;
    const int lane = tid & 31;
    const int warp = tid >> 5;
    const int wm   = warp >> 2;       // 0..1
    const int wn   = warp & 3;        // 0..3

    const long long ldAe = 2LL * Kdim;            // elements per row
    const long long ldBytes = ldAe * 2;
    const char* baseA = (const char*)(A2 + (long long)blockIdx.z * sA + (long long)m0 * ldAe);
    const char* baseB = (const char*)(B2 + (long long)blockIdx.z * sB + (long long)n0 * ldAe);

    const int segK = KBOUND ? (m0 + 128) : Kdim;
    const int nps = segK >> 6;                    // 64-elem chunks per segment
    const int nChunks = 3 * nps;

    // ---- staging mapping: thread -> (row, 16B chunk)
    const int srow = tid >> 3;                    // 0..31
    const int su   = tid & 7;                     // 0..7
    const uint32_t sdst = (uint32_t)(srow * 128 + ((su ^ (srow & 7)) << 4));
    const long long sgoff = (long long)srow * ldBytes + su * 16;

    auto stage = [&](int c, int buf) {
        const int seg = c / nps, kc = c - seg * nps;
        const long long offA = ((long long)kc * 64 + (seg == 2 ? (long long)Kdim : 0)) * 2;
        const long long offB = ((long long)kc * 64 + (seg == 1 ? (long long)Kdim : 0)) * 2;
        const char* ga = baseA + offA + sgoff;
        const char* gb = baseB + offB + sgoff;
        const uint32_t da = sb + buf * 32768u + sdst;
        const uint32_t db = da + 16384u;
#pragma unroll
        for (int i = 0; i < 4; i++) {
            CP_ASYNC_16(da + i * 4096u, ga + (long long)i * 32 * ldBytes);
            CP_ASYNC_16(db + i * 4096u, gb + (long long)i * 32 * ldBytes);
        }
        CP_COMMIT();
    };

    float acc[4][4][4];
#pragma unroll
    for (int i = 0; i < 4; i++)
#pragma unroll
        for (int j = 0; j < 4; j++)
#pragma unroll
            for (int t = 0; t < 4; t++) acc[i][j][t] = 0.f;

    // per-lane ldmatrix address components (XOR swizzle: chunk ^= row&7)
    const uint32_t aRowBase = (uint32_t)(wm * 64 + (lane & 15));
    const uint32_t aChunkX  = (uint32_t)(lane >> 4);
    const uint32_t bRowBase = (uint32_t)(wn * 32 + (lane & 7) + ((lane & 16) >> 1));
    const uint32_t bChunkX  = (uint32_t)((lane >> 3) & 1);
    const uint32_t lxor     = (uint32_t)(lane & 7);

    stage(0, 0);
    stage(1, 1);

    for (int c = 0; c < nChunks; c++) {
        if (c + 1 < nChunks) { CP_WAIT_1(); } else { CP_WAIT_0(); }
        __syncthreads();

        const uint32_t sA = sb + (uint32_t)(c % 3) * 32768u;
        const uint32_t sB = sA + 16384u;

#pragma unroll
        for (int s = 0; s < 4; s++) {
            uint32_t a[4][4];
            uint32_t b[4][2];
#pragma unroll
            for (int mb = 0; mb < 4; mb++) {
                const uint32_t addr = sA + (aRowBase + mb * 16) * 128u
                                    + (((s * 2 + aChunkX) ^ lxor) << 4);
                LDSM_X4(a[mb][0], a[mb][1], a[mb][2], a[mb][3], addr);
            }
#pragma unroll
            for (int nb2 = 0; nb2 < 2; nb2++) {
                const uint32_t addr = sB + (bRowBase + nb2 * 16) * 128u
                                    + (((s * 2 + bChunkX) ^ lxor) << 4);
                LDSM_X4(b[nb2 * 2][0], b[nb2 * 2][1],
                        b[nb2 * 2 + 1][0], b[nb2 * 2 + 1][1], addr);
            }
#pragma unroll
            for (int mb = 0; mb < 4; mb++)
#pragma unroll
                for (int nb = 0; nb < 4; nb++)
                    MMA_BF16(acc[mb][nb], a[mb], b[nb]);
        }

        if (c + 2 < nChunks) stage(c + 2, (c + 2) % 3);
    }

    // ---- epilogue ----------------------------------------------------------
    const int rBase = m0 + wm * 64 + (lane >> 2);
    const int cBase = n0 + wn * 32 + (lane & 3) * 2;

    if (EPI_SPLIT) {
        // write bf16 hi/lo planes: row length 2*Ndim, hi @ [n], lo @ [Ndim+n]
        unsigned short* Cs = (unsigned short*)Cv + (long long)blockIdx.z * sC;
#pragma unroll
        for (int nb = 0; nb < 4; nb++) {
            const int cc = cBase + nb * 8;
            float bx = 0.f, by = 0.f;
            if (HAS_BIAS) { bx = bias[cc]; by = bias[cc + 1]; }
#pragma unroll
            for (int mb = 0; mb < 4; mb++) {
                const int r = rBase + mb * 16;
#pragma unroll
                for (int half = 0; half < 2; half++) {
                    const float v0 = acc[mb][nb][half * 2]     + bx;
                    const float v1 = acc[mb][nb][half * 2 + 1] + by;
                    unsigned short h0, l0, h1, l1;
                    split1(v0, h0, l0);
                    split1(v1, h1, l1);
                    unsigned short* row = Cs + (long long)(r + half * 8) * (2 * Ndim);
                    *(uint32_t*)(row + cc)        = (uint32_t)h0 | ((uint32_t)h1 << 16);
                    *(uint32_t*)(row + Ndim + cc) = (uint32_t)l0 | ((uint32_t)l1 << 16);
                }
            }
        }
    } else {
        float* Cb = (float*)Cv + (long long)blockIdx.z * sC;
#pragma unroll
        for (int nb = 0; nb < 4; nb++) {
            const int cc = cBase + nb * 8;
            float bx = 0.f, by = 0.f;
            if (HAS_BIAS) { bx = bias[cc]; by = bias[cc + 1]; }
#pragma unroll
            for (int mb = 0; mb < 4; mb++) {
                const int r = rBase + mb * 16;
                float2 v0, v1;
                v0.x = acc[mb][nb][0] + bx; v0.y = acc[mb][nb][1] + by;
                v1.x = acc[mb][nb][2] + bx; v1.y = acc[mb][nb][3] + by;
                *(float2*)(Cb + (long long)r * Ndim + cc)       = v0;
                *(float2*)(Cb + (long long)(r + 8) * Ndim + cc) = v1;
            }
        }
    }
}

// ===========================================================================
// Register-resident causal softmax, emits bf16 hi/lo split planes directly.
// One block (256 thr) per row; 8 elements/thread (S = 2048).
// Writes [0, blockEnd) of both planes where blockEnd = (q/128+1)*128; masked
// lanes produce exact 0 -> the zero tail the K-bounded PV GEMM needs.
// ===========================================================================
__global__ __launch_bounds__(256) void softmax_split(
    const float* __restrict__ P, unsigned short* __restrict__ P2)
{
    using namespace cfg;
    const int row = blockIdx.x;          // 0 .. B*S-1
    const int b   = row / S;
    const int q   = row - b * S;
    const float* src = P + (long long)b * S * S + (long long)q * S;
    unsigned short* dst = P2 + ((long long)b * S + q) * (2 * S);
    const int len = q + 1;
    const int blockEnd = ((q >> 7) + 1) << 7;
    const int tid = threadIdx.x;

    __shared__ float red[256];

    // load the whole row (vectorized); values at i >= len are masked later
    float v[8];
#pragma unroll
    for (int j = 0; j < 2; j++)
        *(float4*)&v[j * 4] = *(const float4*)(src + (tid + j * 256) * 4);

    // masked max
    float m = -3.4e38f;
#pragma unroll
    for (int j = 0; j < 2; j++)
#pragma unroll
        for (int t = 0; t < 4; t++) {
            const int i = (tid + j * 256) * 4 + t;
            if (i < len) m = fmaxf(m, v[j * 4 + t]);
        }
    red[tid] = m;
    __syncthreads();
#pragma unroll
    for (int s2 = 128; s2 > 0; s2 >>= 1) {
        if (tid < s2) red[tid] = fmaxf(red[tid], red[tid + s2]);
        __syncthreads();
    }
    m = red[0];
    __syncthreads();

    // masked exp + sum (kept in registers)
    float e[8];
    float sum = 0.f;
#pragma unroll
    for (int j = 0; j < 2; j++)
#pragma unroll
        for (int t = 0; t < 4; t++) {
            const int i = (tid + j * 256) * 4 + t;
            const float ev = (i < len) ? __expf(v[j * 4 + t] - m) : 0.f;
            e[j * 4 + t] = ev;
            sum += ev;
        }
    red[tid] = sum;
    __syncthreads();
#pragma unroll
    for (int s2 = 128; s2 > 0; s2 >>= 1) {
        if (tid < s2) red[tid] += red[tid + s2];
        __syncthreads();
    }
    const float inv = 1.f / red[0];

    // normalize + split-write both planes over [0, blockEnd)
#pragma unroll
    for (int j = 0; j < 2; j++) {
        const int i = (tid + j * 256) * 4;
        if (i < blockEnd) {
            unsigned short h[4], l[4];
#pragma unroll
            for (int t = 0; t < 4; t++) split1(e[j * 4 + t] * inv, h[t], l[t]);
            uint2 hv, lv;
            hv.x = (uint32_t)h[0] | ((uint32_t)h[1] << 16);
            hv.y = (uint32_t)h[2] | ((uint32_t)h[3] << 16);
            lv.x = (uint32_t)l[0] | ((uint32_t)l[1] << 16);
            lv.y = (uint32_t)l[2] | ((uint32_t)l[3] << 16);
            *(uint2*)(dst + i)     = hv;
            *(uint2*)(dst + S + i) = lv;
        }
    }
}

// ===========================================================================
// launch
// ===========================================================================
extern "C" void kernel_launch(void* const* d_in, const int* in_sizes, int n_in,
                              void* d_out, int out_size)
{
    using namespace cfg;
    const float* x  = (const float*)d_in[0];
    const float* Wq = (const float*)d_in[1];
    const float* bq = (const float*)d_in[2];
    const float* Wk = (const float*)d_in[3];
    const float* bk = (const float*)d_in[4];
    const float* Wv = (const float*)d_in[5];
    const float* bv = (const float*)d_in[6];
    float* out = (float*)d_out;

    float *v, *p;
    unsigned short *x2, *wq2, *wk2, *wv2, *q2, *k2, *v2t, *p2;
    cudaGetSymbolAddress((void**)&v, g_v);
    cudaGetSymbolAddress((void**)&p, g_p);
    cudaGetSymbolAddress((void**)&x2,  g_x2);
    cudaGetSymbolAddress((void**)&wq2, g_wq2);
    cudaGetSymbolAddress((void**)&wk2, g_wk2);
    cudaGetSymbolAddress((void**)&wv2, g_wv2);
    cudaGetSymbolAddress((void**)&q2,  g_q2);
    cudaGetSymbolAddress((void**)&k2,  g_k2);
    cudaGetSymbolAddress((void**)&v2t, g_v2t);
    cudaGetSymbolAddress((void**)&p2,  g_p2);

    const int SMEM_DYN = 98304;   // 3 stages x (16KB A + 16KB B)
    cudaFuncSetAttribute(mma_gemm<true,  false, false, true>,
                         cudaFuncAttributeMaxDynamicSharedMemorySize, SMEM_DYN);
    cudaFuncSetAttribute(mma_gemm<true,  false, false, false>,
                         cudaFuncAttributeMaxDynamicSharedMemorySize, SMEM_DYN);
    cudaFuncSetAttribute(mma_gemm<false, true,  false, false>,
                         cudaFuncAttributeMaxDynamicSharedMemorySize, SMEM_DYN);
    cudaFuncSetAttribute(mma_gemm<false, false, true,  false>,
                         cudaFuncAttributeMaxDynamicSharedMemorySize, SMEM_DYN);

    // 1) split x into hi/lo bf16 planes
    conv_split<<<8192, 256>>>(x, x2, (unsigned)(MR * D / 4), (unsigned)(D / 4), D);
    // 2) W^T hi/lo (transpose + split)
    {
        dim3 g(D / 32, D / 32, 1), b2(32, 8);
        conv_split_T<<<g, b2>>>(Wq, wq2, D, D, 0, 0);
        conv_split_T<<<g, b2>>>(Wk, wk2, D, D, 0, 0);
        conv_split_T<<<g, b2>>>(Wv, wv2, D, D, 0, 0);
    }
    // 3) projections: Q,K -> split planes directly; V -> fp32
    {
        dim3 g(D / 128, MR / 128, 1), b2(256);
        mma_gemm<true, false, false, true ><<<g, b2, SMEM_DYN>>>(x2, wq2, bq, q2, D, D, 0, 0, 0);
        mma_gemm<true, false, false, true ><<<g, b2, SMEM_DYN>>>(x2, wk2, bk, k2, D, D, 0, 0, 0);
        mma_gemm<true, false, false, false><<<g, b2, SMEM_DYN>>>(x2, wv2, bv, v,  D, D, 0, 0, 0);
    }
    // 4) scores = q k^T per batch (causal tile skip)
    {
        dim3 g(S / 128, S / 128, B), b2(256);
        mma_gemm<false, true, false, false><<<g, b2, SMEM_DYN>>>(
            q2, k2, nullptr, p, S, D,
            (long long)S * 2 * D, (long long)S * 2 * D, (long long)S * S);
    }
    // 5) softmax + split (register-resident, emits p2 directly)
    softmax_split<<<B * S, 256>>>(p, p2);
    // 6) V^T hi/lo per batch
    {
        dim3 g(D / 32, S / 32, B), b2(32, 8);
        conv_split_T<<<g, b2>>>(v, v2t, S, D, (long long)S * D, (long long)D * 2 * S);
    }
    // 7) out = P V per batch (K bounded by causal structure)
    {
        dim3 g(D / 128, S / 128, B), b2(256);
        mma_gemm<false, false, true, false><<<g, b2, SMEM_DYN>>>(
            p2, v2t, nullptr, out, D, S,
            (long long)S * 2 * S, (long long)D * 2 * S, (long long)S * D);
    }
}